// round 2
// baseline (speedup 1.0000x reference)
#include <cuda_runtime.h>
#include <math.h>

#define NTOK   8192
#define DMODEL 768
#define DFFN   3072
#define NH     12
#define DHD    64
#define SEQ    1024
#define NBATCH 8
#define LN_EPS 1e-6f

// ---------------- scratch (static device globals; no allocation) ----------------
__device__ float g_q [NTOK * DMODEL];
__device__ float g_k [NTOK * DMODEL];
__device__ float g_v [NTOK * DMODEL];
__device__ float g_o [NTOK * DMODEL];
__device__ float g_h [NTOK * DMODEL];
__device__ float g_h2[NTOK * DMODEL];
__device__ float g_f [NTOK * DFFN];
__device__ float g_t [NTOK * DMODEL];

// ---------------- GEMM: C[M,N] = A[M,K] @ W[N,K]^T + bias (+ epilogue) ----------
// kind: 0 = bias, 1 = bias + residual, 2 = bias + exact GELU
// Tiles: BM=BN=128, BK=16, 256 threads, 8x8 microtile. All dims divide exactly.
__global__ void __launch_bounds__(256)
gemm_kernel(const float* __restrict__ A, const float* __restrict__ W,
            const float* __restrict__ bias, const float* __restrict__ res,
            float* __restrict__ C, int M, int N, int K, int kind)
{
    __shared__ float As[16][128];
    __shared__ float Bs[16][128];

    const int tid = threadIdx.x;
    const int bm  = blockIdx.y * 128;
    const int bn  = blockIdx.x * 128;
    const int tx  = tid & 15;        // 0..15 -> col group
    const int ty  = tid >> 4;        // 0..15 -> row group

    float acc[8][8];
#pragma unroll
    for (int i = 0; i < 8; i++)
#pragma unroll
        for (int j = 0; j < 8; j++) acc[i][j] = 0.f;

    const int v0 = tid * 2;          // two float4 loads per operand per thread

    for (int k0 = 0; k0 < K; k0 += 16) {
#pragma unroll
        for (int l = 0; l < 2; l++) {
            int v   = v0 + l;
            int row = v >> 2;              // 0..127
            int c4  = (v & 3) * 4;         // 0,4,8,12
            float4 av = *(const float4*)&A[(long)(bm + row) * K + k0 + c4];
            As[c4 + 0][row] = av.x; As[c4 + 1][row] = av.y;
            As[c4 + 2][row] = av.z; As[c4 + 3][row] = av.w;
            float4 bv = *(const float4*)&W[(long)(bn + row) * K + k0 + c4];
            Bs[c4 + 0][row] = bv.x; Bs[c4 + 1][row] = bv.y;
            Bs[c4 + 2][row] = bv.z; Bs[c4 + 3][row] = bv.w;
        }
        __syncthreads();

#pragma unroll
        for (int kk = 0; kk < 16; kk++) {
            float a[8], b[8];
#pragma unroll
            for (int i = 0; i < 8; i++) a[i] = As[kk][ty * 8 + i];
#pragma unroll
            for (int j = 0; j < 8; j++) b[j] = Bs[kk][tx * 8 + j];
#pragma unroll
            for (int i = 0; i < 8; i++)
#pragma unroll
                for (int j = 0; j < 8; j++)
                    acc[i][j] = fmaf(a[i], b[j], acc[i][j]);
        }
        __syncthreads();
    }

#pragma unroll
    for (int i = 0; i < 8; i++) {
        int m = bm + ty * 8 + i;
#pragma unroll
        for (int j = 0; j < 8; j++) {
            int n = bn + tx * 8 + j;
            float val = acc[i][j] + bias[n];
            if (kind == 1) {
                val += res[(long)m * N + n];
            } else if (kind == 2) {
                val = 0.5f * val * (1.0f + erff(val * 0.70710678118654752f));
            }
            C[(long)m * N + n] = val;
        }
    }
}

// ---------------- Flash attention: one CTA = (b, h, 64-query block) -------------
// smem: K/V tiles only (2 * 64 * 65 * 4 = 33,280 B < 48 KB). Q row lives in regs.
__global__ void __launch_bounds__(64)
attn_kernel(const float* __restrict__ Q, const float* __restrict__ Kp,
            const float* __restrict__ Vp, float* __restrict__ O)
{
    const int qb = blockIdx.x;   // 0..15
    const int h  = blockIdx.y;   // 0..11
    const int b  = blockIdx.z;   // 0..7
    const int t  = threadIdx.x;  // 0..63 -> one query row

    __shared__ float sk[64][DHD + 1];
    __shared__ float sv[64][DHD + 1];

    const int base_q = b * SEQ + qb * 64;
    const int hoff   = h * DHD;

    // each thread loads its own q row directly (one-time cost)
    float qr[DHD];
    {
        const float4* qp = (const float4*)&Q[(long)(base_q + t) * DMODEL + hoff];
#pragma unroll
        for (int d4 = 0; d4 < DHD / 4; d4++) {
            float4 qv4 = qp[d4];
            qr[d4 * 4 + 0] = qv4.x; qr[d4 * 4 + 1] = qv4.y;
            qr[d4 * 4 + 2] = qv4.z; qr[d4 * 4 + 3] = qv4.w;
        }
    }

    float acc[DHD];
#pragma unroll
    for (int d = 0; d < DHD; d++) acc[d] = 0.f;
    float mrow = -1e30f, lrow = 0.f;

    for (int kb = 0; kb < SEQ / 64; kb++) {
        __syncthreads();   // protect sk/sv reuse
        const int base_k = b * SEQ + kb * 64;
        for (int r = 0; r < 64; r++) {
            sk[r][t] = Kp[(long)(base_k + r) * DMODEL + hoff + t];
            sv[r][t] = Vp[(long)(base_k + r) * DMODEL + hoff + t];
        }
        __syncthreads();

        // 16-key chunks: bounded registers, all smem reads broadcast
        for (int jb = 0; jb < 64; jb += 16) {
            float s[16];
#pragma unroll
            for (int jj = 0; jj < 16; jj++) {
                float a = 0.f;
#pragma unroll
                for (int d = 0; d < DHD; d++)
                    a = fmaf(qr[d], sk[jb + jj][d], a);
                s[jj] = a * 0.125f;   // 1/sqrt(64)
            }
            float mnew = mrow;
#pragma unroll
            for (int jj = 0; jj < 16; jj++) mnew = fmaxf(mnew, s[jj]);
            float corr = __expf(mrow - mnew);
            mrow = mnew;
            lrow *= corr;
#pragma unroll
            for (int d = 0; d < DHD; d++) acc[d] *= corr;
#pragma unroll
            for (int jj = 0; jj < 16; jj++) {
                float p = __expf(s[jj] - mnew);
                lrow += p;
#pragma unroll
                for (int d = 0; d < DHD; d++)
                    acc[d] = fmaf(p, sv[jb + jj][d], acc[d]);
            }
        }
    }

    const float inv = 1.f / lrow;
#pragma unroll
    for (int d = 0; d < DHD; d++)
        O[(long)(base_q + t) * DMODEL + hoff + d] = acc[d] * inv;
}

// ---------------- LayerNorm: one row per CTA, 256 threads -----------------------
__global__ void __launch_bounds__(256)
ln_kernel(const float* __restrict__ X, const float* __restrict__ gam,
          const float* __restrict__ bet, float* __restrict__ Y)
{
    const int row = blockIdx.x;
    const int t   = threadIdx.x;
    const int lane = t & 31, wid = t >> 5;
    const float* x = X + (long)row * DMODEL;

    float v0 = x[t], v1 = x[t + 256], v2 = x[t + 512];
    float s = v0 + v1 + v2;

    __shared__ float sbuf[8];
    __shared__ float s_mu, s_rstd;

#pragma unroll
    for (int o = 16; o > 0; o >>= 1) s += __shfl_xor_sync(~0u, s, o);
    if (lane == 0) sbuf[wid] = s;
    __syncthreads();
    if (t == 0) {
        float tot = 0.f;
        for (int i = 0; i < 8; i++) tot += sbuf[i];
        s_mu = tot * (1.0f / DMODEL);
    }
    __syncthreads();
    const float mu = s_mu;

    float d0 = v0 - mu, d1 = v1 - mu, d2 = v2 - mu;
    float qv = d0 * d0 + d1 * d1 + d2 * d2;
#pragma unroll
    for (int o = 16; o > 0; o >>= 1) qv += __shfl_xor_sync(~0u, qv, o);
    if (lane == 0) sbuf[wid] = qv;
    __syncthreads();
    if (t == 0) {
        float tot = 0.f;
        for (int i = 0; i < 8; i++) tot += sbuf[i];
        s_rstd = rsqrtf(tot * (1.0f / DMODEL) + LN_EPS);
    }
    __syncthreads();
    const float rstd = s_rstd;

    Y[(long)row * DMODEL + t      ] = d0 * rstd * gam[t      ] + bet[t      ];
    Y[(long)row * DMODEL + t + 256] = d1 * rstd * gam[t + 256] + bet[t + 256];
    Y[(long)row * DMODEL + t + 512] = d2 * rstd * gam[t + 512] + bet[t + 512];
}

// ---------------- launch --------------------------------------------------------
extern "C" void kernel_launch(void* const* d_in, const int* in_sizes, int n_in,
                              void* d_out, int out_size)
{
    const float* x    = (const float*)d_in[0];
    const float* x1   = (const float*)d_in[1];
    const float* Wq   = (const float*)d_in[2];
    const float* bq   = (const float*)d_in[3];
    const float* Wk   = (const float*)d_in[4];
    const float* bk   = (const float*)d_in[5];
    const float* Wv   = (const float*)d_in[6];
    const float* bv   = (const float*)d_in[7];
    const float* Wo   = (const float*)d_in[8];
    const float* bo   = (const float*)d_in[9];
    const float* W1   = (const float*)d_in[10];
    const float* b1   = (const float*)d_in[11];
    const float* W2   = (const float*)d_in[12];
    const float* b2   = (const float*)d_in[13];
    const float* ln1g = (const float*)d_in[14];
    const float* ln1b = (const float*)d_in[15];
    const float* ln2g = (const float*)d_in[16];
    const float* ln2b = (const float*)d_in[17];
    float* out = (float*)d_out;

    float *q, *k, *v, *o, *h, *h2, *f, *tbuf;
    cudaGetSymbolAddress((void**)&q,    g_q);
    cudaGetSymbolAddress((void**)&k,    g_k);
    cudaGetSymbolAddress((void**)&v,    g_v);
    cudaGetSymbolAddress((void**)&o,    g_o);
    cudaGetSymbolAddress((void**)&h,    g_h);
    cudaGetSymbolAddress((void**)&h2,   g_h2);
    cudaGetSymbolAddress((void**)&f,    g_f);
    cudaGetSymbolAddress((void**)&tbuf, g_t);

    dim3 blk(256);
    dim3 g768(DMODEL / 128, NTOK / 128);   // (6, 64)
    dim3 gffn(DFFN / 128, NTOK / 128);     // (24, 64)

    // Q/K/V projections
    gemm_kernel<<<g768, blk>>>(x,  Wq, bq, nullptr, q, NTOK, DMODEL, DMODEL, 0);
    gemm_kernel<<<g768, blk>>>(x1, Wk, bk, nullptr, k, NTOK, DMODEL, DMODEL, 0);
    gemm_kernel<<<g768, blk>>>(x1, Wv, bv, nullptr, v, NTOK, DMODEL, DMODEL, 0);

    // attention
    attn_kernel<<<dim3(SEQ / 64, NH, NBATCH), 64>>>(q, k, v, o);

    // output projection + residual -> h
    gemm_kernel<<<g768, blk>>>(o, Wo, bo, x, h, NTOK, DMODEL, DMODEL, 1);

    // h2 = LN(h, ln2)
    ln_kernel<<<NTOK, 256>>>(h, ln2g, ln2b, h2);

    // FFN
    gemm_kernel<<<gffn, blk>>>(h2, W1, b1, nullptr, f, NTOK, DFFN, DMODEL, 2);
    gemm_kernel<<<g768, blk>>>(f,  W2, b2, h, tbuf, NTOK, DMODEL, DFFN, 1);

    // out = LN(h + ffn, ln1)
    ln_kernel<<<NTOK, 256>>>(tbuf, ln1g, ln1b, out);
}

// round 5
// speedup vs baseline: 1.5931x; 1.5931x over previous
#include <cuda_runtime.h>
#include <math.h>
#include <stdint.h>

#define NTOK   8192
#define DMODEL 768
#define DFFN   3072
#define NH     12
#define DHD    64
#define SEQ    1024
#define NBATCH 8
#define LN_EPS 1e-6f

// ---------------- scratch (static device globals; no allocation) ----------------
__device__ float g_q [NTOK * DMODEL];
__device__ float g_k [NTOK * DMODEL];
__device__ float g_v [NTOK * DMODEL];
__device__ float g_o [NTOK * DMODEL];
__device__ float g_h [NTOK * DMODEL];
__device__ float g_h2[NTOK * DMODEL];
__device__ float g_f [NTOK * DFFN];
__device__ float g_t [NTOK * DMODEL];

// ---------------- helpers ---------------------------------------------------------
__device__ __forceinline__ uint32_t cvt_tf32(float f) {
    uint32_t r; asm("cvt.rna.tf32.f32 %0, %1;" : "=r"(r) : "f"(f)); return r;
}

__device__ __forceinline__ void mma16n8k8(float d[4],
                                          uint32_t a0, uint32_t a1, uint32_t a2, uint32_t a3,
                                          uint32_t b0, uint32_t b1) {
    asm volatile("mma.sync.aligned.m16n8k8.row.col.f32.tf32.tf32.f32 "
                 "{%0,%1,%2,%3}, {%4,%5,%6,%7}, {%8,%9}, {%0,%1,%2,%3};"
                 : "+f"(d[0]), "+f"(d[1]), "+f"(d[2]), "+f"(d[3])
                 : "r"(a0), "r"(a1), "r"(a2), "r"(a3), "r"(b0), "r"(b1));
}

// ---------------- mma.sync tf32 GEMM ----------------------------------------------
// C[M,N] = A[M,K] @ W[N,K]^T + bias (+ epilogue). kind: 0=bias, 1=+res, 2=+GELU.
// CTA 128x128, 8 warps (2x4), warp tile 64x32. K-chunks of 32, double-buffered smem.
// Smem tiles padded to 36 words/row -> fragment LDS pattern is bank-conflict-free.
#define PADK   36
#define TILE_W (128 * PADK)        // words per operand tile
#define BUF_W  (2 * TILE_W)        // words per buffer (A + B)

__global__ void __launch_bounds__(256)
gemm_mma(const float* __restrict__ A, const float* __restrict__ W,
         const float* __restrict__ bias, const float* __restrict__ res,
         float* __restrict__ C, int M, int N, int K, int kind)
{
    extern __shared__ uint32_t smem[];   // 2 buffers x (A tile + B tile)

    const int tid  = threadIdx.x;
    const int wid  = tid >> 5;
    const int lane = tid & 31;
    const int g    = lane >> 2;        // group id 0..7
    const int tig  = lane & 3;         // thread in group 0..3
    const int bm   = blockIdx.y * 128, bn = blockIdx.x * 128;
    const int wm   = (wid >> 2) * 64;  // warp m offset (0/64)
    const int wn   = (wid & 3) * 32;   // warp n offset (0/32/64/96)

    float d[4][4][4];
#pragma unroll
    for (int mi = 0; mi < 4; mi++)
#pragma unroll
        for (int ni = 0; ni < 4; ni++)
#pragma unroll
            for (int e = 0; e < 4; e++) d[mi][ni][e] = 0.f;

    // global load mapping: 2 threads per row, each 4 float4 (64B)
    const int grow  = tid >> 1;
    const int ghalf = (tid & 1) * 16;

    const float* aptr = &A[(size_t)(bm + grow) * K + ghalf];
    const float* bptr = &W[(size_t)(bn + grow) * K + ghalf];

    float4 ra[4], rb[4];
#pragma unroll
    for (int i = 0; i < 4; i++) {
        ra[i] = *(const float4*)&aptr[i * 4];
        rb[i] = *(const float4*)&bptr[i * 4];
    }

    const int NC = K >> 5;

    // store chunk regs -> smem buffer (tf32-converted)
    auto sts = [&](uint32_t* sbuf) {
        uint32_t* sa = &sbuf[grow * PADK + ghalf];
        uint32_t* sb = &sbuf[TILE_W + grow * PADK + ghalf];
#pragma unroll
        for (int i = 0; i < 4; i++) {
            sa[i * 4 + 0] = cvt_tf32(ra[i].x); sa[i * 4 + 1] = cvt_tf32(ra[i].y);
            sa[i * 4 + 2] = cvt_tf32(ra[i].z); sa[i * 4 + 3] = cvt_tf32(ra[i].w);
            sb[i * 4 + 0] = cvt_tf32(rb[i].x); sb[i * 4 + 1] = cvt_tf32(rb[i].y);
            sb[i * 4 + 2] = cvt_tf32(rb[i].z); sb[i * 4 + 3] = cvt_tf32(rb[i].w);
        }
    };

    sts(smem);
    __syncthreads();

    for (int c = 0; c < NC; c++) {
        const int b = c & 1;

        // prefetch next chunk while computing this one
        if (c + 1 < NC) {
            const float* ap = aptr + ((c + 1) << 5);
            const float* bp = bptr + ((c + 1) << 5);
#pragma unroll
            for (int i = 0; i < 4; i++) {
                ra[i] = *(const float4*)&ap[i * 4];
                rb[i] = *(const float4*)&bp[i * 4];
            }
        }

        const uint32_t* sA = &smem[b * BUF_W];
        const uint32_t* sB = &smem[b * BUF_W + TILE_W];

#pragma unroll
        for (int ks = 0; ks < 4; ks++) {
            const int kc = ks * 8;
            uint32_t afr[4][4], bfr[4][2];
#pragma unroll
            for (int mi = 0; mi < 4; mi++) {
                const uint32_t* p = &sA[(wm + mi * 16 + g) * PADK + kc + tig];
                afr[mi][0] = p[0];
                afr[mi][2] = p[4];
                afr[mi][1] = p[8 * PADK];
                afr[mi][3] = p[8 * PADK + 4];
            }
#pragma unroll
            for (int ni = 0; ni < 4; ni++) {
                const uint32_t* p = &sB[(wn + ni * 8 + g) * PADK + kc + tig];
                bfr[ni][0] = p[0];
                bfr[ni][1] = p[4];
            }
#pragma unroll
            for (int mi = 0; mi < 4; mi++)
#pragma unroll
                for (int ni = 0; ni < 4; ni++)
                    mma16n8k8(d[mi][ni], afr[mi][0], afr[mi][1], afr[mi][2], afr[mi][3],
                              bfr[ni][0], bfr[ni][1]);
        }

        __syncthreads();
        if (c + 1 < NC) {
            sts(&smem[(b ^ 1) * BUF_W]);
            __syncthreads();
        }
    }

    // epilogue: fragment (mi,ni): rows wm+mi*16+g / +8, cols wn+ni*8+2*tig / +1
#pragma unroll
    for (int mi = 0; mi < 4; mi++) {
#pragma unroll
        for (int rh = 0; rh < 2; rh++) {
            const int m = bm + wm + mi * 16 + g + rh * 8;
            float* crow = &C[(size_t)m * N];
            const float* rrow = res ? &res[(size_t)m * N] : nullptr;
#pragma unroll
            for (int ni = 0; ni < 4; ni++) {
                const int n = bn + wn + ni * 8 + 2 * tig;
                float v0 = d[mi][ni][rh * 2 + 0] + bias[n];
                float v1 = d[mi][ni][rh * 2 + 1] + bias[n + 1];
                if (kind == 1) {
                    v0 += rrow[n]; v1 += rrow[n + 1];
                } else if (kind == 2) {
                    v0 = 0.5f * v0 * (1.0f + erff(v0 * 0.70710678118654752f));
                    v1 = 0.5f * v1 * (1.0f + erff(v1 * 0.70710678118654752f));
                }
                *(float2*)&crow[n] = make_float2(v0, v1);
            }
        }
    }
}

// ---------------- Flash attention: one CTA = (b, h, 64-query block) -------------
__global__ void __launch_bounds__(64)
attn_kernel(const float* __restrict__ Q, const float* __restrict__ Kp,
            const float* __restrict__ Vp, float* __restrict__ O)
{
    const int qb = blockIdx.x;
    const int h  = blockIdx.y;
    const int b  = blockIdx.z;
    const int t  = threadIdx.x;

    __shared__ float sk[64][DHD + 1];
    __shared__ float sv[64][DHD + 1];

    const int base_q = b * SEQ + qb * 64;
    const int hoff   = h * DHD;

    float qr[DHD];
    {
        const float4* qp = (const float4*)&Q[(size_t)(base_q + t) * DMODEL + hoff];
#pragma unroll
        for (int d4 = 0; d4 < DHD / 4; d4++) {
            float4 qv4 = qp[d4];
            qr[d4 * 4 + 0] = qv4.x; qr[d4 * 4 + 1] = qv4.y;
            qr[d4 * 4 + 2] = qv4.z; qr[d4 * 4 + 3] = qv4.w;
        }
    }

    float acc[DHD];
#pragma unroll
    for (int d = 0; d < DHD; d++) acc[d] = 0.f;
    float mrow = -1e30f, lrow = 0.f;

    for (int kb = 0; kb < SEQ / 64; kb++) {
        __syncthreads();
        const int base_k = b * SEQ + kb * 64;
        for (int r = 0; r < 64; r++) {
            sk[r][t] = Kp[(size_t)(base_k + r) * DMODEL + hoff + t];
            sv[r][t] = Vp[(size_t)(base_k + r) * DMODEL + hoff + t];
        }
        __syncthreads();

        for (int jb = 0; jb < 64; jb += 16) {
            float s[16];
#pragma unroll
            for (int jj = 0; jj < 16; jj++) {
                float a = 0.f;
#pragma unroll
                for (int d = 0; d < DHD; d++)
                    a = fmaf(qr[d], sk[jb + jj][d], a);
                s[jj] = a * 0.125f;
            }
            float mnew = mrow;
#pragma unroll
            for (int jj = 0; jj < 16; jj++) mnew = fmaxf(mnew, s[jj]);
            float corr = __expf(mrow - mnew);
            mrow = mnew;
            lrow *= corr;
#pragma unroll
            for (int d = 0; d < DHD; d++) acc[d] *= corr;
#pragma unroll
            for (int jj = 0; jj < 16; jj++) {
                float p = __expf(s[jj] - mnew);
                lrow += p;
#pragma unroll
                for (int d = 0; d < DHD; d++)
                    acc[d] = fmaf(p, sv[jb + jj][d], acc[d]);
            }
        }
    }

    const float inv = 1.f / lrow;
#pragma unroll
    for (int d = 0; d < DHD; d++)
        O[(size_t)(base_q + t) * DMODEL + hoff + d] = acc[d] * inv;
}

// ---------------- LayerNorm: one row per CTA, 256 threads -----------------------
__global__ void __launch_bounds__(256)
ln_kernel(const float* __restrict__ X, const float* __restrict__ gam,
          const float* __restrict__ bet, float* __restrict__ Y)
{
    const int row = blockIdx.x;
    const int t   = threadIdx.x;
    const int lane = t & 31, wid = t >> 5;
    const float* x = X + (size_t)row * DMODEL;

    float v0 = x[t], v1 = x[t + 256], v2 = x[t + 512];
    float s = v0 + v1 + v2;

    __shared__ float sbuf[8];
    __shared__ float s_mu, s_rstd;

#pragma unroll
    for (int o = 16; o > 0; o >>= 1) s += __shfl_xor_sync(~0u, s, o);
    if (lane == 0) sbuf[wid] = s;
    __syncthreads();
    if (t == 0) {
        float tot = 0.f;
        for (int i = 0; i < 8; i++) tot += sbuf[i];
        s_mu = tot * (1.0f / DMODEL);
    }
    __syncthreads();
    const float mu = s_mu;

    float d0 = v0 - mu, d1 = v1 - mu, d2 = v2 - mu;
    float qv = d0 * d0 + d1 * d1 + d2 * d2;
#pragma unroll
    for (int o = 16; o > 0; o >>= 1) qv += __shfl_xor_sync(~0u, qv, o);
    if (lane == 0) sbuf[wid] = qv;
    __syncthreads();
    if (t == 0) {
        float tot = 0.f;
        for (int i = 0; i < 8; i++) tot += sbuf[i];
        s_rstd = rsqrtf(tot * (1.0f / DMODEL) + LN_EPS);
    }
    __syncthreads();
    const float rstd = s_rstd;

    Y[(size_t)row * DMODEL + t      ] = d0 * rstd * gam[t      ] + bet[t      ];
    Y[(size_t)row * DMODEL + t + 256] = d1 * rstd * gam[t + 256] + bet[t + 256];
    Y[(size_t)row * DMODEL + t + 512] = d2 * rstd * gam[t + 512] + bet[t + 512];
}

// ---------------- launch --------------------------------------------------------
extern "C" void kernel_launch(void* const* d_in, const int* in_sizes, int n_in,
                              void* d_out, int out_size)
{
    const float* x    = (const float*)d_in[0];
    const float* x1   = (const float*)d_in[1];
    const float* Wq   = (const float*)d_in[2];
    const float* bq   = (const float*)d_in[3];
    const float* Wk   = (const float*)d_in[4];
    const float* bk   = (const float*)d_in[5];
    const float* Wv   = (const float*)d_in[6];
    const float* bv   = (const float*)d_in[7];
    const float* Wo   = (const float*)d_in[8];
    const float* bo   = (const float*)d_in[9];
    const float* W1   = (const float*)d_in[10];
    const float* b1   = (const float*)d_in[11];
    const float* W2   = (const float*)d_in[12];
    const float* b2   = (const float*)d_in[13];
    const float* ln1g = (const float*)d_in[14];
    const float* ln1b = (const float*)d_in[15];
    const float* ln2g = (const float*)d_in[16];
    const float* ln2b = (const float*)d_in[17];
    float* out = (float*)d_out;

    float *q, *k, *v, *o, *h, *h2, *f, *tbuf;
    cudaGetSymbolAddress((void**)&q,    g_q);
    cudaGetSymbolAddress((void**)&k,    g_k);
    cudaGetSymbolAddress((void**)&v,    g_v);
    cudaGetSymbolAddress((void**)&o,    g_o);
    cudaGetSymbolAddress((void**)&h,    g_h);
    cudaGetSymbolAddress((void**)&h2,   g_h2);
    cudaGetSymbolAddress((void**)&f,    g_f);
    cudaGetSymbolAddress((void**)&tbuf, g_t);

    const int SMB = 2 * BUF_W * 4;   // 73,728 bytes
    cudaFuncSetAttribute(gemm_mma, cudaFuncAttributeMaxDynamicSharedMemorySize, SMB);

    dim3 blk(256);
    dim3 g768(DMODEL / 128, NTOK / 128);   // (6, 64)
    dim3 gffn(DFFN / 128, NTOK / 128);     // (24, 64)

    gemm_mma<<<g768, blk, SMB>>>(x,  Wq, bq, nullptr, q, NTOK, DMODEL, DMODEL, 0);
    gemm_mma<<<g768, blk, SMB>>>(x1, Wk, bk, nullptr, k, NTOK, DMODEL, DMODEL, 0);
    gemm_mma<<<g768, blk, SMB>>>(x1, Wv, bv, nullptr, v, NTOK, DMODEL, DMODEL, 0);

    attn_kernel<<<dim3(SEQ / 64, NH, NBATCH), 64>>>(q, k, v, o);

    gemm_mma<<<g768, blk, SMB>>>(o, Wo, bo, x, h, NTOK, DMODEL, DMODEL, 1);

    ln_kernel<<<NTOK, 256>>>(h, ln2g, ln2b, h2);

    gemm_mma<<<gffn, blk, SMB>>>(h2, W1, b1, nullptr, f, NTOK, DFFN, DMODEL, 2);
    gemm_mma<<<g768, blk, SMB>>>(f,  W2, b2, h, tbuf, NTOK, DMODEL, DFFN, 1);

    ln_kernel<<<NTOK, 256>>>(tbuf, ln1g, ln1b, out);
}

// round 6
// speedup vs baseline: 1.6838x; 1.0570x over previous
#include <cuda_runtime.h>
#include <math.h>
#include <stdint.h>

#define NTOK   8192
#define DMODEL 768
#define DFFN   3072
#define NH     12
#define DHD    64
#define SEQ    1024
#define NBATCH 8
#define LN_EPS 1e-6f

// ---------------- scratch (static device globals; no allocation) ----------------
__device__ float g_q [NTOK * DMODEL];
__device__ float g_k [NTOK * DMODEL];
__device__ float g_v [NTOK * DMODEL];
__device__ float g_o [NTOK * DMODEL];
__device__ float g_h [NTOK * DMODEL];
__device__ float g_h2[NTOK * DMODEL];
__device__ float g_f [NTOK * DFFN];
__device__ float g_t [NTOK * DMODEL];

// ---------------- helpers ---------------------------------------------------------
__device__ __forceinline__ uint32_t cvt_tf32(float f) {
    uint32_t r; asm("cvt.rna.tf32.f32 %0, %1;" : "=r"(r) : "f"(f)); return r;
}

__device__ __forceinline__ void mma16n8k8(float d[4],
                                          uint32_t a0, uint32_t a1, uint32_t a2, uint32_t a3,
                                          uint32_t b0, uint32_t b1) {
    asm volatile("mma.sync.aligned.m16n8k8.row.col.f32.tf32.tf32.f32 "
                 "{%0,%1,%2,%3}, {%4,%5,%6,%7}, {%8,%9}, {%0,%1,%2,%3};"
                 : "+f"(d[0]), "+f"(d[1]), "+f"(d[2]), "+f"(d[3])
                 : "r"(a0), "r"(a1), "r"(a2), "r"(a3), "r"(b0), "r"(b1));
}

// ---------------- mma.sync tf32 GEMM ----------------------------------------------
// C[M,N] = A[M,K] @ W[N,K]^T + bias (+ epilogue). kind: 0=bias, 1=+res, 2=+GELU.
// CTA 128x128, 8 warps (2x4), warp tile 64x32. K-chunks of 32, double-buffered smem.
#define PADK   36
#define TILE_W (128 * PADK)        // words per operand tile
#define BUF_W  (2 * TILE_W)        // words per buffer (A + B)

__global__ void __launch_bounds__(256)
gemm_mma(const float* __restrict__ A, const float* __restrict__ W,
         const float* __restrict__ bias, const float* __restrict__ res,
         float* __restrict__ C, int M, int N, int K, int kind)
{
    extern __shared__ uint32_t smem[];   // 2 buffers x (A tile + B tile)

    const int tid  = threadIdx.x;
    const int wid  = tid >> 5;
    const int lane = tid & 31;
    const int g    = lane >> 2;        // group id 0..7
    const int tig  = lane & 3;         // thread in group 0..3
    const int bm   = blockIdx.y * 128, bn = blockIdx.x * 128;
    const int wm   = (wid >> 2) * 64;  // warp m offset (0/64)
    const int wn   = (wid & 3) * 32;   // warp n offset (0/32/64/96)

    float d[4][4][4];
#pragma unroll
    for (int mi = 0; mi < 4; mi++)
#pragma unroll
        for (int ni = 0; ni < 4; ni++)
#pragma unroll
            for (int e = 0; e < 4; e++) d[mi][ni][e] = 0.f;

    // global load mapping: 2 threads per row, each 4 float4 (64B)
    const int grow  = tid >> 1;
    const int ghalf = (tid & 1) * 16;

    const float* aptr = &A[(size_t)(bm + grow) * K + ghalf];
    const float* bptr = &W[(size_t)(bn + grow) * K + ghalf];

    float4 ra[4], rb[4];
#pragma unroll
    for (int i = 0; i < 4; i++) {
        ra[i] = *(const float4*)&aptr[i * 4];
        rb[i] = *(const float4*)&bptr[i * 4];
    }

    const int NC = K >> 5;

    auto sts = [&](uint32_t* sbuf) {
        uint32_t* sa = &sbuf[grow * PADK + ghalf];
        uint32_t* sb = &sbuf[TILE_W + grow * PADK + ghalf];
#pragma unroll
        for (int i = 0; i < 4; i++) {
            sa[i * 4 + 0] = cvt_tf32(ra[i].x); sa[i * 4 + 1] = cvt_tf32(ra[i].y);
            sa[i * 4 + 2] = cvt_tf32(ra[i].z); sa[i * 4 + 3] = cvt_tf32(ra[i].w);
            sb[i * 4 + 0] = cvt_tf32(rb[i].x); sb[i * 4 + 1] = cvt_tf32(rb[i].y);
            sb[i * 4 + 2] = cvt_tf32(rb[i].z); sb[i * 4 + 3] = cvt_tf32(rb[i].w);
        }
    };

    sts(smem);
    __syncthreads();

    for (int c = 0; c < NC; c++) {
        const int b = c & 1;

        if (c + 1 < NC) {
            const float* ap = aptr + ((c + 1) << 5);
            const float* bp = bptr + ((c + 1) << 5);
#pragma unroll
            for (int i = 0; i < 4; i++) {
                ra[i] = *(const float4*)&ap[i * 4];
                rb[i] = *(const float4*)&bp[i * 4];
            }
        }

        const uint32_t* sA = &smem[b * BUF_W];
        const uint32_t* sB = &smem[b * BUF_W + TILE_W];

#pragma unroll
        for (int ks = 0; ks < 4; ks++) {
            const int kc = ks * 8;
            uint32_t afr[4][4], bfr[4][2];
#pragma unroll
            for (int mi = 0; mi < 4; mi++) {
                const uint32_t* p = &sA[(wm + mi * 16 + g) * PADK + kc + tig];
                afr[mi][0] = p[0];
                afr[mi][2] = p[4];
                afr[mi][1] = p[8 * PADK];
                afr[mi][3] = p[8 * PADK + 4];
            }
#pragma unroll
            for (int ni = 0; ni < 4; ni++) {
                const uint32_t* p = &sB[(wn + ni * 8 + g) * PADK + kc + tig];
                bfr[ni][0] = p[0];
                bfr[ni][1] = p[4];
            }
#pragma unroll
            for (int mi = 0; mi < 4; mi++)
#pragma unroll
                for (int ni = 0; ni < 4; ni++)
                    mma16n8k8(d[mi][ni], afr[mi][0], afr[mi][1], afr[mi][2], afr[mi][3],
                              bfr[ni][0], bfr[ni][1]);
        }

        __syncthreads();
        if (c + 1 < NC) {
            sts(&smem[(b ^ 1) * BUF_W]);
            __syncthreads();
        }
    }

    // epilogue
#pragma unroll
    for (int mi = 0; mi < 4; mi++) {
#pragma unroll
        for (int rh = 0; rh < 2; rh++) {
            const int m = bm + wm + mi * 16 + g + rh * 8;
            float* crow = &C[(size_t)m * N];
            const float* rrow = res ? &res[(size_t)m * N] : nullptr;
#pragma unroll
            for (int ni = 0; ni < 4; ni++) {
                const int n = bn + wn + ni * 8 + 2 * tig;
                float v0 = d[mi][ni][rh * 2 + 0] + bias[n];
                float v1 = d[mi][ni][rh * 2 + 1] + bias[n + 1];
                if (kind == 1) {
                    v0 += rrow[n]; v1 += rrow[n + 1];
                } else if (kind == 2) {
                    v0 = 0.5f * v0 * (1.0f + erff(v0 * 0.70710678118654752f));
                    v1 = 0.5f * v1 * (1.0f + erff(v1 * 0.70710678118654752f));
                }
                *(float2*)&crow[n] = make_float2(v0, v1);
            }
        }
    }
}

// ---------------- Flash attention: one CTA = (b, h, 64-query block) -------------
// K/V tiles stored as float4[64][17]: row stride 272B (16B-aligned) -> LDS.128.
__global__ void __launch_bounds__(64)
attn_kernel(const float* __restrict__ Q, const float* __restrict__ Kp,
            const float* __restrict__ Vp, float* __restrict__ O)
{
    const int qb = blockIdx.x;
    const int h  = blockIdx.y;
    const int b  = blockIdx.z;
    const int t  = threadIdx.x;

    __shared__ float4 sk4[64][17];
    __shared__ float4 sv4[64][17];

    const int base_q = b * SEQ + qb * 64;
    const int hoff   = h * DHD;

    float4 qr[16];
    {
        const float4* qp = (const float4*)&Q[(size_t)(base_q + t) * DMODEL + hoff];
#pragma unroll
        for (int dq = 0; dq < 16; dq++) qr[dq] = qp[dq];
    }

    float4 acc[16];
#pragma unroll
    for (int dq = 0; dq < 16; dq++) acc[dq] = make_float4(0.f, 0.f, 0.f, 0.f);
    float mrow = -1e30f, lrow = 0.f;

    for (int kb = 0; kb < SEQ / 64; kb++) {
        __syncthreads();
        const int base_k = b * SEQ + kb * 64;
        for (int r = 0; r < 64; r++) {
            ((float*)&sk4[r][0])[t] = Kp[(size_t)(base_k + r) * DMODEL + hoff + t];
            ((float*)&sv4[r][0])[t] = Vp[(size_t)(base_k + r) * DMODEL + hoff + t];
        }
        __syncthreads();

        for (int jb = 0; jb < 64; jb += 16) {
            float s[16];
#pragma unroll
            for (int jj = 0; jj < 16; jj++) {
                float a = 0.f;
#pragma unroll
                for (int dq = 0; dq < 16; dq++) {
                    float4 kk = sk4[jb + jj][dq];
                    a = fmaf(qr[dq].x, kk.x, a);
                    a = fmaf(qr[dq].y, kk.y, a);
                    a = fmaf(qr[dq].z, kk.z, a);
                    a = fmaf(qr[dq].w, kk.w, a);
                }
                s[jj] = a * 0.125f;   // 1/sqrt(64)
            }
            float mnew = mrow;
#pragma unroll
            for (int jj = 0; jj < 16; jj++) mnew = fmaxf(mnew, s[jj]);
            float corr = __expf(mrow - mnew);
            mrow = mnew;
            lrow *= corr;
#pragma unroll
            for (int dq = 0; dq < 16; dq++) {
                acc[dq].x *= corr; acc[dq].y *= corr;
                acc[dq].z *= corr; acc[dq].w *= corr;
            }
#pragma unroll
            for (int jj = 0; jj < 16; jj++) {
                float p = __expf(s[jj] - mnew);
                lrow += p;
#pragma unroll
                for (int dq = 0; dq < 16; dq++) {
                    float4 vv = sv4[jb + jj][dq];
                    acc[dq].x = fmaf(p, vv.x, acc[dq].x);
                    acc[dq].y = fmaf(p, vv.y, acc[dq].y);
                    acc[dq].z = fmaf(p, vv.z, acc[dq].z);
                    acc[dq].w = fmaf(p, vv.w, acc[dq].w);
                }
            }
        }
    }

    const float inv = 1.f / lrow;
    float4* op = (float4*)&O[(size_t)(base_q + t) * DMODEL + hoff];
#pragma unroll
    for (int dq = 0; dq < 16; dq++) {
        float4 r = acc[dq];
        r.x *= inv; r.y *= inv; r.z *= inv; r.w *= inv;
        op[dq] = r;
    }
}

// ---------------- LayerNorm: one row per CTA, 256 threads -----------------------
__global__ void __launch_bounds__(256)
ln_kernel(const float* __restrict__ X, const float* __restrict__ gam,
          const float* __restrict__ bet, float* __restrict__ Y)
{
    const int row = blockIdx.x;
    const int t   = threadIdx.x;
    const int lane = t & 31, wid = t >> 5;
    const float* x = X + (size_t)row * DMODEL;

    float v0 = x[t], v1 = x[t + 256], v2 = x[t + 512];
    float s = v0 + v1 + v2;

    __shared__ float sbuf[8];
    __shared__ float s_mu, s_rstd;

#pragma unroll
    for (int o = 16; o > 0; o >>= 1) s += __shfl_xor_sync(~0u, s, o);
    if (lane == 0) sbuf[wid] = s;
    __syncthreads();
    if (t == 0) {
        float tot = 0.f;
        for (int i = 0; i < 8; i++) tot += sbuf[i];
        s_mu = tot * (1.0f / DMODEL);
    }
    __syncthreads();
    const float mu = s_mu;

    float d0 = v0 - mu, d1 = v1 - mu, d2 = v2 - mu;
    float qv = d0 * d0 + d1 * d1 + d2 * d2;
#pragma unroll
    for (int o = 16; o > 0; o >>= 1) qv += __shfl_xor_sync(~0u, qv, o);
    if (lane == 0) sbuf[wid] = qv;
    __syncthreads();
    if (t == 0) {
        float tot = 0.f;
        for (int i = 0; i < 8; i++) tot += sbuf[i];
        s_rstd = rsqrtf(tot * (1.0f / DMODEL) + LN_EPS);
    }
    __syncthreads();
    const float rstd = s_rstd;

    Y[(size_t)row * DMODEL + t      ] = d0 * rstd * gam[t      ] + bet[t      ];
    Y[(size_t)row * DMODEL + t + 256] = d1 * rstd * gam[t + 256] + bet[t + 256];
    Y[(size_t)row * DMODEL + t + 512] = d2 * rstd * gam[t + 512] + bet[t + 512];
}

// ---------------- launch --------------------------------------------------------
extern "C" void kernel_launch(void* const* d_in, const int* in_sizes, int n_in,
                              void* d_out, int out_size)
{
    const float* x    = (const float*)d_in[0];
    const float* x1   = (const float*)d_in[1];
    const float* Wq   = (const float*)d_in[2];
    const float* bq   = (const float*)d_in[3];
    const float* Wk   = (const float*)d_in[4];
    const float* bk   = (const float*)d_in[5];
    const float* Wv   = (const float*)d_in[6];
    const float* bv   = (const float*)d_in[7];
    const float* Wo   = (const float*)d_in[8];
    const float* bo   = (const float*)d_in[9];
    const float* W1   = (const float*)d_in[10];
    const float* b1   = (const float*)d_in[11];
    const float* W2   = (const float*)d_in[12];
    const float* b2   = (const float*)d_in[13];
    const float* ln1g = (const float*)d_in[14];
    const float* ln1b = (const float*)d_in[15];
    const float* ln2g = (const float*)d_in[16];
    const float* ln2b = (const float*)d_in[17];
    float* out = (float*)d_out;

    float *q, *k, *v, *o, *h, *h2, *f, *tbuf;
    cudaGetSymbolAddress((void**)&q,    g_q);
    cudaGetSymbolAddress((void**)&k,    g_k);
    cudaGetSymbolAddress((void**)&v,    g_v);
    cudaGetSymbolAddress((void**)&o,    g_o);
    cudaGetSymbolAddress((void**)&h,    g_h);
    cudaGetSymbolAddress((void**)&h2,   g_h2);
    cudaGetSymbolAddress((void**)&f,    g_f);
    cudaGetSymbolAddress((void**)&tbuf, g_t);

    const int SMB = 2 * BUF_W * 4;   // 73,728 bytes
    cudaFuncSetAttribute(gemm_mma, cudaFuncAttributeMaxDynamicSharedMemorySize, SMB);

    dim3 blk(256);
    dim3 g768(DMODEL / 128, NTOK / 128);   // (6, 64)
    dim3 gffn(DFFN / 128, NTOK / 128);     // (24, 64)

    gemm_mma<<<g768, blk, SMB>>>(x,  Wq, bq, nullptr, q, NTOK, DMODEL, DMODEL, 0);
    gemm_mma<<<g768, blk, SMB>>>(x1, Wk, bk, nullptr, k, NTOK, DMODEL, DMODEL, 0);
    gemm_mma<<<g768, blk, SMB>>>(x1, Wv, bv, nullptr, v, NTOK, DMODEL, DMODEL, 0);

    attn_kernel<<<dim3(SEQ / 64, NH, NBATCH), 64>>>(q, k, v, o);

    gemm_mma<<<g768, blk, SMB>>>(o, Wo, bo, x, h, NTOK, DMODEL, DMODEL, 1);

    ln_kernel<<<NTOK, 256>>>(h, ln2g, ln2b, h2);

    gemm_mma<<<gffn, blk, SMB>>>(h2, W1, b1, nullptr, f, NTOK, DFFN, DMODEL, 2);
    gemm_mma<<<g768, blk, SMB>>>(f,  W2, b2, h, tbuf, NTOK, DMODEL, DFFN, 1);

    ln_kernel<<<NTOK, 256>>>(tbuf, ln1g, ln1b, out);
}

// round 7
// speedup vs baseline: 1.9484x; 1.1571x over previous
#include <cuda_runtime.h>
#include <cuda_fp16.h>
#include <math.h>
#include <stdint.h>

#define NTOK   8192
#define DMODEL 768
#define DFFN   3072
#define NH     12
#define DHD    64
#define SEQ    1024
#define NBATCH 8
#define LN_EPS 1e-6f

// ---------------- scratch (static device globals; no allocation) ----------------
__device__ float g_q [NTOK * DMODEL];
__device__ float g_k [NTOK * DMODEL];
__device__ float g_v [NTOK * DMODEL];
__device__ float g_o [NTOK * DMODEL];
__device__ float g_h [NTOK * DMODEL];
__device__ float g_h2[NTOK * DMODEL];
__device__ float g_f [NTOK * DFFN];
__device__ float g_t [NTOK * DMODEL];

// ---------------- helpers ---------------------------------------------------------
__device__ __forceinline__ uint32_t h2_u32(half2 h) {
    uint32_t r; asm("mov.b32 %0, %1;" : "=r"(r) : "r"(*(uint32_t*)&h)); return r;
}

__device__ __forceinline__ void mma16n8k16(float d[4],
                                           uint32_t a0, uint32_t a1, uint32_t a2, uint32_t a3,
                                           uint32_t b0, uint32_t b1) {
    asm volatile("mma.sync.aligned.m16n8k16.row.col.f32.f16.f16.f32 "
                 "{%0,%1,%2,%3}, {%4,%5,%6,%7}, {%8,%9}, {%0,%1,%2,%3};"
                 : "+f"(d[0]), "+f"(d[1]), "+f"(d[2]), "+f"(d[3])
                 : "r"(a0), "r"(a1), "r"(a2), "r"(a3), "r"(b0), "r"(b1));
}

// ---------------- mma.sync fp16 GEMM ----------------------------------------------
// C[M,N] = A[M,K] @ W[N,K]^T + bias (+ epilogue). kind: 0=bias, 1=+res, 2=+GELU.
// CTA 128x128, 8 warps (2x4), warp tile 64x32. K-chunks of 32, double-buffered smem.
// smem in half2 units, row stride PADH2=20 -> all fragment LDS conflict-free.
#define PADH2   20
#define TILE_H2 (128 * PADH2)      // half2 words per operand tile
#define BUF_H2  (2 * TILE_H2)      // half2 words per buffer (A + B)

__global__ void __launch_bounds__(256)
gemm_mma(const float* __restrict__ A, const float* __restrict__ W,
         const float* __restrict__ bias, const float* __restrict__ res,
         float* __restrict__ C, int M, int N, int K, int kind)
{
    extern __shared__ uint32_t smem[];   // 2 buffers x (A tile + B tile), half2 per word

    const int tid  = threadIdx.x;
    const int wid  = tid >> 5;
    const int lane = tid & 31;
    const int g    = lane >> 2;        // group id 0..7
    const int tig  = lane & 3;         // thread in group 0..3
    const int bm   = blockIdx.y * 128, bn = blockIdx.x * 128;
    const int wm   = (wid >> 2) * 64;  // warp m offset (0/64)
    const int wn   = (wid & 3) * 32;   // warp n offset (0/32/64/96)

    float d[4][4][4];
#pragma unroll
    for (int mi = 0; mi < 4; mi++)
#pragma unroll
        for (int ni = 0; ni < 4; ni++)
#pragma unroll
            for (int e = 0; e < 4; e++) d[mi][ni][e] = 0.f;

    // global load mapping: 2 threads per row, each 4 float4 (64B = 16 floats)
    const int grow  = tid >> 1;
    const int ghalf = (tid & 1) * 16;  // float offset; = 8 half2

    const float* aptr = &A[(size_t)(bm + grow) * K + ghalf];
    const float* bptr = &W[(size_t)(bn + grow) * K + ghalf];

    float4 ra[4], rb[4];
#pragma unroll
    for (int i = 0; i < 4; i++) {
        ra[i] = *(const float4*)&aptr[i * 4];
        rb[i] = *(const float4*)&bptr[i * 4];
    }

    const int NC = K >> 5;

    // store chunk regs -> smem buffer (fp16-converted, half2 packed)
    auto sts = [&](uint32_t* sbuf) {
        uint32_t* sa = &sbuf[grow * PADH2 + (tid & 1) * 8];
        uint32_t* sb = &sbuf[TILE_H2 + grow * PADH2 + (tid & 1) * 8];
#pragma unroll
        for (int i = 0; i < 4; i++) {
            sa[i * 2 + 0] = h2_u32(__floats2half2_rn(ra[i].x, ra[i].y));
            sa[i * 2 + 1] = h2_u32(__floats2half2_rn(ra[i].z, ra[i].w));
            sb[i * 2 + 0] = h2_u32(__floats2half2_rn(rb[i].x, rb[i].y));
            sb[i * 2 + 1] = h2_u32(__floats2half2_rn(rb[i].z, rb[i].w));
        }
    };

    sts(smem);
    __syncthreads();

    for (int c = 0; c < NC; c++) {
        const int b = c & 1;

        // prefetch next chunk while computing this one
        if (c + 1 < NC) {
            const float* ap = aptr + ((c + 1) << 5);
            const float* bp = bptr + ((c + 1) << 5);
#pragma unroll
            for (int i = 0; i < 4; i++) {
                ra[i] = *(const float4*)&ap[i * 4];
                rb[i] = *(const float4*)&bp[i * 4];
            }
        }

        const uint32_t* sA = &smem[b * BUF_H2];
        const uint32_t* sB = &smem[b * BUF_H2 + TILE_H2];

#pragma unroll
        for (int ks = 0; ks < 2; ks++) {          // two k16 steps per 32-chunk
            const int kc = ks * 8;                // half2 offset within row
            uint32_t afr[4][4], bfr[4][2];
#pragma unroll
            for (int mi = 0; mi < 4; mi++) {
                const uint32_t* p  = &sA[(wm + mi * 16 + g) * PADH2 + kc + tig];
                const uint32_t* p2 = p + 8 * PADH2;
                afr[mi][0] = p[0];    // (row g,   k 2tig..2tig+1)
                afr[mi][1] = p2[0];   // (row g+8, k-low)
                afr[mi][2] = p[4];    // (row g,   k-high)
                afr[mi][3] = p2[4];   // (row g+8, k-high)
            }
#pragma unroll
            for (int ni = 0; ni < 4; ni++) {
                const uint32_t* p = &sB[(wn + ni * 8 + g) * PADH2 + kc + tig];
                bfr[ni][0] = p[0];
                bfr[ni][1] = p[4];
            }
#pragma unroll
            for (int mi = 0; mi < 4; mi++)
#pragma unroll
                for (int ni = 0; ni < 4; ni++)
                    mma16n8k16(d[mi][ni], afr[mi][0], afr[mi][1], afr[mi][2], afr[mi][3],
                               bfr[ni][0], bfr[ni][1]);
        }

        __syncthreads();
        if (c + 1 < NC) {
            sts(&smem[(b ^ 1) * BUF_H2]);
            __syncthreads();
        }
    }

    // epilogue: fragment (mi,ni): rows wm+mi*16+g / +8, cols wn+ni*8+2*tig / +1
#pragma unroll
    for (int mi = 0; mi < 4; mi++) {
#pragma unroll
        for (int rh = 0; rh < 2; rh++) {
            const int m = bm + wm + mi * 16 + g + rh * 8;
            float* crow = &C[(size_t)m * N];
            const float* rrow = res ? &res[(size_t)m * N] : nullptr;
#pragma unroll
            for (int ni = 0; ni < 4; ni++) {
                const int n = bn + wn + ni * 8 + 2 * tig;
                float v0 = d[mi][ni][rh * 2 + 0] + bias[n];
                float v1 = d[mi][ni][rh * 2 + 1] + bias[n + 1];
                if (kind == 1) {
                    v0 += rrow[n]; v1 += rrow[n + 1];
                } else if (kind == 2) {
                    v0 = 0.5f * v0 * (1.0f + erff(v0 * 0.70710678118654752f));
                    v1 = 0.5f * v1 * (1.0f + erff(v1 * 0.70710678118654752f));
                }
                *(float2*)&crow[n] = make_float2(v0, v1);
            }
        }
    }
}

// ---------------- Flash attention: one CTA = (b, h, 64-query block) -------------
// K/V tiles stored as float4[64][17]: row stride 272B (16B-aligned) -> LDS.128.
__global__ void __launch_bounds__(64)
attn_kernel(const float* __restrict__ Q, const float* __restrict__ Kp,
            const float* __restrict__ Vp, float* __restrict__ O)
{
    const int qb = blockIdx.x;
    const int h  = blockIdx.y;
    const int b  = blockIdx.z;
    const int t  = threadIdx.x;

    __shared__ float4 sk4[64][17];
    __shared__ float4 sv4[64][17];

    const int base_q = b * SEQ + qb * 64;
    const int hoff   = h * DHD;

    float4 qr[16];
    {
        const float4* qp = (const float4*)&Q[(size_t)(base_q + t) * DMODEL + hoff];
#pragma unroll
        for (int dq = 0; dq < 16; dq++) qr[dq] = qp[dq];
    }

    float4 acc[16];
#pragma unroll
    for (int dq = 0; dq < 16; dq++) acc[dq] = make_float4(0.f, 0.f, 0.f, 0.f);
    float mrow = -1e30f, lrow = 0.f;

    for (int kb = 0; kb < SEQ / 64; kb++) {
        __syncthreads();
        const int base_k = b * SEQ + kb * 64;
        for (int r = 0; r < 64; r++) {
            ((float*)&sk4[r][0])[t] = Kp[(size_t)(base_k + r) * DMODEL + hoff + t];
            ((float*)&sv4[r][0])[t] = Vp[(size_t)(base_k + r) * DMODEL + hoff + t];
        }
        __syncthreads();

        for (int jb = 0; jb < 64; jb += 16) {
            float s[16];
#pragma unroll
            for (int jj = 0; jj < 16; jj++) {
                float a = 0.f;
#pragma unroll
                for (int dq = 0; dq < 16; dq++) {
                    float4 kk = sk4[jb + jj][dq];
                    a = fmaf(qr[dq].x, kk.x, a);
                    a = fmaf(qr[dq].y, kk.y, a);
                    a = fmaf(qr[dq].z, kk.z, a);
                    a = fmaf(qr[dq].w, kk.w, a);
                }
                s[jj] = a * 0.125f;   // 1/sqrt(64)
            }
            float mnew = mrow;
#pragma unroll
            for (int jj = 0; jj < 16; jj++) mnew = fmaxf(mnew, s[jj]);
            float corr = __expf(mrow - mnew);
            mrow = mnew;
            lrow *= corr;
#pragma unroll
            for (int dq = 0; dq < 16; dq++) {
                acc[dq].x *= corr; acc[dq].y *= corr;
                acc[dq].z *= corr; acc[dq].w *= corr;
            }
#pragma unroll
            for (int jj = 0; jj < 16; jj++) {
                float p = __expf(s[jj] - mnew);
                lrow += p;
#pragma unroll
                for (int dq = 0; dq < 16; dq++) {
                    float4 vv = sv4[jb + jj][dq];
                    acc[dq].x = fmaf(p, vv.x, acc[dq].x);
                    acc[dq].y = fmaf(p, vv.y, acc[dq].y);
                    acc[dq].z = fmaf(p, vv.z, acc[dq].z);
                    acc[dq].w = fmaf(p, vv.w, acc[dq].w);
                }
            }
        }
    }

    const float inv = 1.f / lrow;
    float4* op = (float4*)&O[(size_t)(base_q + t) * DMODEL + hoff];
#pragma unroll
    for (int dq = 0; dq < 16; dq++) {
        float4 r = acc[dq];
        r.x *= inv; r.y *= inv; r.z *= inv; r.w *= inv;
        op[dq] = r;
    }
}

// ---------------- LayerNorm: one row per CTA, 256 threads -----------------------
__global__ void __launch_bounds__(256)
ln_kernel(const float* __restrict__ X, const float* __restrict__ gam,
          const float* __restrict__ bet, float* __restrict__ Y)
{
    const int row = blockIdx.x;
    const int t   = threadIdx.x;
    const int lane = t & 31, wid = t >> 5;
    const float* x = X + (size_t)row * DMODEL;

    float v0 = x[t], v1 = x[t + 256], v2 = x[t + 512];
    float s = v0 + v1 + v2;

    __shared__ float sbuf[8];
    __shared__ float s_mu, s_rstd;

#pragma unroll
    for (int o = 16; o > 0; o >>= 1) s += __shfl_xor_sync(~0u, s, o);
    if (lane == 0) sbuf[wid] = s;
    __syncthreads();
    if (t == 0) {
        float tot = 0.f;
        for (int i = 0; i < 8; i++) tot += sbuf[i];
        s_mu = tot * (1.0f / DMODEL);
    }
    __syncthreads();
    const float mu = s_mu;

    float d0 = v0 - mu, d1 = v1 - mu, d2 = v2 - mu;
    float qv = d0 * d0 + d1 * d1 + d2 * d2;
#pragma unroll
    for (int o = 16; o > 0; o >>= 1) qv += __shfl_xor_sync(~0u, qv, o);
    if (lane == 0) sbuf[wid] = qv;
    __syncthreads();
    if (t == 0) {
        float tot = 0.f;
        for (int i = 0; i < 8; i++) tot += sbuf[i];
        s_rstd = rsqrtf(tot * (1.0f / DMODEL) + LN_EPS);
    }
    __syncthreads();
    const float rstd = s_rstd;

    Y[(size_t)row * DMODEL + t      ] = d0 * rstd * gam[t      ] + bet[t      ];
    Y[(size_t)row * DMODEL + t + 256] = d1 * rstd * gam[t + 256] + bet[t + 256];
    Y[(size_t)row * DMODEL + t + 512] = d2 * rstd * gam[t + 512] + bet[t + 512];
}

// ---------------- launch --------------------------------------------------------
extern "C" void kernel_launch(void* const* d_in, const int* in_sizes, int n_in,
                              void* d_out, int out_size)
{
    const float* x    = (const float*)d_in[0];
    const float* x1   = (const float*)d_in[1];
    const float* Wq   = (const float*)d_in[2];
    const float* bq   = (const float*)d_in[3];
    const float* Wk   = (const float*)d_in[4];
    const float* bk   = (const float*)d_in[5];
    const float* Wv   = (const float*)d_in[6];
    const float* bv   = (const float*)d_in[7];
    const float* Wo   = (const float*)d_in[8];
    const float* bo   = (const float*)d_in[9];
    const float* W1   = (const float*)d_in[10];
    const float* b1   = (const float*)d_in[11];
    const float* W2   = (const float*)d_in[12];
    const float* b2   = (const float*)d_in[13];
    const float* ln1g = (const float*)d_in[14];
    const float* ln1b = (const float*)d_in[15];
    const float* ln2g = (const float*)d_in[16];
    const float* ln2b = (const float*)d_in[17];
    float* out = (float*)d_out;

    float *q, *k, *v, *o, *h, *h2, *f, *tbuf;
    cudaGetSymbolAddress((void**)&q,    g_q);
    cudaGetSymbolAddress((void**)&k,    g_k);
    cudaGetSymbolAddress((void**)&v,    g_v);
    cudaGetSymbolAddress((void**)&o,    g_o);
    cudaGetSymbolAddress((void**)&h,    g_h);
    cudaGetSymbolAddress((void**)&h2,   g_h2);
    cudaGetSymbolAddress((void**)&f,    g_f);
    cudaGetSymbolAddress((void**)&tbuf, g_t);

    const int SMB = 2 * BUF_H2 * 4;   // 40,960 bytes
    cudaFuncSetAttribute(gemm_mma, cudaFuncAttributeMaxDynamicSharedMemorySize, SMB);

    dim3 blk(256);
    dim3 g768(DMODEL / 128, NTOK / 128);   // (6, 64)
    dim3 gffn(DFFN / 128, NTOK / 128);     // (24, 64)

    gemm_mma<<<g768, blk, SMB>>>(x,  Wq, bq, nullptr, q, NTOK, DMODEL, DMODEL, 0);
    gemm_mma<<<g768, blk, SMB>>>(x1, Wk, bk, nullptr, k, NTOK, DMODEL, DMODEL, 0);
    gemm_mma<<<g768, blk, SMB>>>(x1, Wv, bv, nullptr, v, NTOK, DMODEL, DMODEL, 0);

    attn_kernel<<<dim3(SEQ / 64, NH, NBATCH), 64>>>(q, k, v, o);

    gemm_mma<<<g768, blk, SMB>>>(o, Wo, bo, x, h, NTOK, DMODEL, DMODEL, 1);

    ln_kernel<<<NTOK, 256>>>(h, ln2g, ln2b, h2);

    gemm_mma<<<gffn, blk, SMB>>>(h2, W1, b1, nullptr, f, NTOK, DFFN, DMODEL, 2);
    gemm_mma<<<g768, blk, SMB>>>(f,  W2, b2, h, tbuf, NTOK, DMODEL, DFFN, 1);

    ln_kernel<<<NTOK, 256>>>(tbuf, ln1g, ln1b, out);
}

// round 8
// speedup vs baseline: 3.3628x; 1.7260x over previous
#include <cuda_runtime.h>
#include <cuda_fp16.h>
#include <math.h>
#include <stdint.h>

#define NTOK   8192
#define DMODEL 768
#define DFFN   3072
#define NH     12
#define DHD    64
#define SEQ    1024
#define NBATCH 8
#define LN_EPS 1e-6f

// ---------------- scratch (static device globals; no allocation) ----------------
__device__ float g_q [NTOK * DMODEL];
__device__ float g_k [NTOK * DMODEL];
__device__ float g_v [NTOK * DMODEL];
__device__ float g_o [NTOK * DMODEL];
__device__ float g_h [NTOK * DMODEL];
__device__ float g_h2[NTOK * DMODEL];
__device__ float g_f [NTOK * DFFN];
__device__ float g_t [NTOK * DMODEL];

// ---------------- helpers ---------------------------------------------------------
__device__ __forceinline__ uint32_t h2_u32(half2 h) {
    return *(uint32_t*)&h;
}

__device__ __forceinline__ void mma16n8k16(float d[4],
                                           uint32_t a0, uint32_t a1, uint32_t a2, uint32_t a3,
                                           uint32_t b0, uint32_t b1) {
    asm volatile("mma.sync.aligned.m16n8k16.row.col.f32.f16.f16.f32 "
                 "{%0,%1,%2,%3}, {%4,%5,%6,%7}, {%8,%9}, {%0,%1,%2,%3};"
                 : "+f"(d[0]), "+f"(d[1]), "+f"(d[2]), "+f"(d[3])
                 : "r"(a0), "r"(a1), "r"(a2), "r"(a3), "r"(b0), "r"(b1));
}

// ---------------- mma.sync fp16 GEMM ----------------------------------------------
#define PADH2   20
#define TILE_H2 (128 * PADH2)
#define BUF_H2  (2 * TILE_H2)

__global__ void __launch_bounds__(256)
gemm_mma(const float* __restrict__ A, const float* __restrict__ W,
         const float* __restrict__ bias, const float* __restrict__ res,
         float* __restrict__ C, int M, int N, int K, int kind)
{
    extern __shared__ uint32_t smem[];

    const int tid  = threadIdx.x;
    const int wid  = tid >> 5;
    const int lane = tid & 31;
    const int g    = lane >> 2;
    const int tig  = lane & 3;
    const int bm   = blockIdx.y * 128, bn = blockIdx.x * 128;
    const int wm   = (wid >> 2) * 64;
    const int wn   = (wid & 3) * 32;

    float d[4][4][4];
#pragma unroll
    for (int mi = 0; mi < 4; mi++)
#pragma unroll
        for (int ni = 0; ni < 4; ni++)
#pragma unroll
            for (int e = 0; e < 4; e++) d[mi][ni][e] = 0.f;

    const int grow  = tid >> 1;
    const int ghalf = (tid & 1) * 16;

    const float* aptr = &A[(size_t)(bm + grow) * K + ghalf];
    const float* bptr = &W[(size_t)(bn + grow) * K + ghalf];

    float4 ra[4], rb[4];
#pragma unroll
    for (int i = 0; i < 4; i++) {
        ra[i] = *(const float4*)&aptr[i * 4];
        rb[i] = *(const float4*)&bptr[i * 4];
    }

    const int NC = K >> 5;

    auto sts = [&](uint32_t* sbuf) {
        uint32_t* sa = &sbuf[grow * PADH2 + (tid & 1) * 8];
        uint32_t* sb = &sbuf[TILE_H2 + grow * PADH2 + (tid & 1) * 8];
#pragma unroll
        for (int i = 0; i < 4; i++) {
            sa[i * 2 + 0] = h2_u32(__floats2half2_rn(ra[i].x, ra[i].y));
            sa[i * 2 + 1] = h2_u32(__floats2half2_rn(ra[i].z, ra[i].w));
            sb[i * 2 + 0] = h2_u32(__floats2half2_rn(rb[i].x, rb[i].y));
            sb[i * 2 + 1] = h2_u32(__floats2half2_rn(rb[i].z, rb[i].w));
        }
    };

    sts(smem);
    __syncthreads();

    for (int c = 0; c < NC; c++) {
        const int b = c & 1;

        if (c + 1 < NC) {
            const float* ap = aptr + ((c + 1) << 5);
            const float* bp = bptr + ((c + 1) << 5);
#pragma unroll
            for (int i = 0; i < 4; i++) {
                ra[i] = *(const float4*)&ap[i * 4];
                rb[i] = *(const float4*)&bp[i * 4];
            }
        }

        const uint32_t* sA = &smem[b * BUF_H2];
        const uint32_t* sB = &smem[b * BUF_H2 + TILE_H2];

#pragma unroll
        for (int ks = 0; ks < 2; ks++) {
            const int kc = ks * 8;
            uint32_t afr[4][4], bfr[4][2];
#pragma unroll
            for (int mi = 0; mi < 4; mi++) {
                const uint32_t* p  = &sA[(wm + mi * 16 + g) * PADH2 + kc + tig];
                const uint32_t* p2 = p + 8 * PADH2;
                afr[mi][0] = p[0];
                afr[mi][1] = p2[0];
                afr[mi][2] = p[4];
                afr[mi][3] = p2[4];
            }
#pragma unroll
            for (int ni = 0; ni < 4; ni++) {
                const uint32_t* p = &sB[(wn + ni * 8 + g) * PADH2 + kc + tig];
                bfr[ni][0] = p[0];
                bfr[ni][1] = p[4];
            }
#pragma unroll
            for (int mi = 0; mi < 4; mi++)
#pragma unroll
                for (int ni = 0; ni < 4; ni++)
                    mma16n8k16(d[mi][ni], afr[mi][0], afr[mi][1], afr[mi][2], afr[mi][3],
                               bfr[ni][0], bfr[ni][1]);
        }

        __syncthreads();
        if (c + 1 < NC) {
            sts(&smem[(b ^ 1) * BUF_H2]);
            __syncthreads();
        }
    }

#pragma unroll
    for (int mi = 0; mi < 4; mi++) {
#pragma unroll
        for (int rh = 0; rh < 2; rh++) {
            const int m = bm + wm + mi * 16 + g + rh * 8;
            float* crow = &C[(size_t)m * N];
            const float* rrow = res ? &res[(size_t)m * N] : nullptr;
#pragma unroll
            for (int ni = 0; ni < 4; ni++) {
                const int n = bn + wn + ni * 8 + 2 * tig;
                float v0 = d[mi][ni][rh * 2 + 0] + bias[n];
                float v1 = d[mi][ni][rh * 2 + 1] + bias[n + 1];
                if (kind == 1) {
                    v0 += rrow[n]; v1 += rrow[n + 1];
                } else if (kind == 2) {
                    v0 = 0.5f * v0 * (1.0f + erff(v0 * 0.70710678118654752f));
                    v1 = 0.5f * v1 * (1.0f + erff(v1 * 0.70710678118654752f));
                }
                *(float2*)&crow[n] = make_float2(v0, v1);
            }
        }
    }
}

// ---------------- Tensor-core flash attention --------------------------------------
// CTA = 128 queries x (b,h), 8 warps, warp = 16 query rows. fp16 mma, fp32 accum.
// sq[128][72], sk[64][72] (K rows = B operand directly), sv = V^T [64 d][72 keys].
#define QPAD 72

__global__ void __launch_bounds__(256)
attn_mma(const float* __restrict__ Qp, const float* __restrict__ Kp,
         const float* __restrict__ Vp, float* __restrict__ Op)
{
    __shared__ half sq[128 * QPAD];
    __shared__ half sk[64 * QPAD];
    __shared__ half sv[64 * QPAD];

    const int tid  = threadIdx.x;
    const int wq   = tid >> 5;
    const int lane = tid & 31;
    const int g    = lane >> 2;
    const int tig  = lane & 3;
    const int qb = blockIdx.x, h = blockIdx.y, b = blockIdx.z;
    const int base_q = b * SEQ + qb * 128;
    const int hoff   = h * DHD;

    // Q tile: 2 threads/row, 8 float4 each -> fp16 smem
    {
        const int r = tid >> 1, c0 = (tid & 1) * 32;
        const float4* qp = (const float4*)&Qp[(size_t)(base_q + r) * DMODEL + hoff + c0];
        half* dst = &sq[r * QPAD + c0];
#pragma unroll
        for (int i = 0; i < 8; i++) {
            float4 v = qp[i];
            *(half2*)&dst[i * 4 + 0] = __floats2half2_rn(v.x, v.y);
            *(half2*)&dst[i * 4 + 2] = __floats2half2_rn(v.z, v.w);
        }
    }
    __syncthreads();

    // hoist Q fragments (loop-invariant)
    uint32_t qf[4][4];
#pragma unroll
    for (int ks = 0; ks < 4; ks++) {
        const half* p = &sq[(wq * 16 + g) * QPAD + ks * 16 + 2 * tig];
        qf[ks][0] = *(const uint32_t*)p;
        qf[ks][1] = *(const uint32_t*)(p + 8 * QPAD);
        qf[ks][2] = *(const uint32_t*)(p + 8);
        qf[ks][3] = *(const uint32_t*)(p + 8 * QPAD + 8);
    }

    float oa[8][4];
#pragma unroll
    for (int no = 0; no < 8; no++)
#pragma unroll
        for (int e = 0; e < 4; e++) oa[no][e] = 0.f;
    float m0 = -1e30f, m1 = -1e30f, l0 = 0.f, l1 = 0.f;

    const float SC  = 0.125f;                 // 1/sqrt(64)
    const float L2E = 1.4426950408889634f;

    for (int kb = 0; kb < SEQ / 64; kb++) {
        __syncthreads();
        const int base_k = b * SEQ + kb * 64;
        {
            const int r = tid >> 2, c0 = (tid & 3) * 16;
            const float4* kp = (const float4*)&Kp[(size_t)(base_k + r) * DMODEL + hoff + c0];
            const float4* vp = (const float4*)&Vp[(size_t)(base_k + r) * DMODEL + hoff + c0];
            half* kdst = &sk[r * QPAD + c0];
#pragma unroll
            for (int i = 0; i < 4; i++) {
                float4 kv = kp[i];
                *(half2*)&kdst[i * 4 + 0] = __floats2half2_rn(kv.x, kv.y);
                *(half2*)&kdst[i * 4 + 2] = __floats2half2_rn(kv.z, kv.w);
                float4 vv = vp[i];
                sv[(c0 + i * 4 + 0) * QPAD + r] = __float2half_rn(vv.x);
                sv[(c0 + i * 4 + 1) * QPAD + r] = __float2half_rn(vv.y);
                sv[(c0 + i * 4 + 2) * QPAD + r] = __float2half_rn(vv.z);
                sv[(c0 + i * 4 + 3) * QPAD + r] = __float2half_rn(vv.w);
            }
        }
        __syncthreads();

        // scores S = Q K^T  (per warp: 16 x 64)
        float sf[8][4];
#pragma unroll
        for (int ni = 0; ni < 8; ni++) {
            sf[ni][0] = sf[ni][1] = sf[ni][2] = sf[ni][3] = 0.f;
            const half* kr = &sk[(ni * 8 + g) * QPAD + 2 * tig];
#pragma unroll
            for (int ks = 0; ks < 4; ks++) {
                uint32_t b0 = *(const uint32_t*)(kr + ks * 16);
                uint32_t b1 = *(const uint32_t*)(kr + ks * 16 + 8);
                mma16n8k16(sf[ni], qf[ks][0], qf[ks][1], qf[ks][2], qf[ks][3], b0, b1);
            }
        }

        // online softmax on fragments
        float mx0 = -1e30f, mx1 = -1e30f;
#pragma unroll
        for (int ni = 0; ni < 8; ni++) {
            mx0 = fmaxf(mx0, fmaxf(sf[ni][0], sf[ni][1]));
            mx1 = fmaxf(mx1, fmaxf(sf[ni][2], sf[ni][3]));
        }
        mx0 *= SC; mx1 *= SC;
        mx0 = fmaxf(mx0, __shfl_xor_sync(~0u, mx0, 1));
        mx0 = fmaxf(mx0, __shfl_xor_sync(~0u, mx0, 2));
        mx1 = fmaxf(mx1, __shfl_xor_sync(~0u, mx1, 1));
        mx1 = fmaxf(mx1, __shfl_xor_sync(~0u, mx1, 2));

        const float mn0 = fmaxf(m0, mx0), mn1 = fmaxf(m1, mx1);
        const float c0f = __expf(m0 - mn0), c1f = __expf(m1 - mn1);
        m0 = mn0; m1 = mn1;
        l0 *= c0f; l1 *= c1f;
#pragma unroll
        for (int no = 0; no < 8; no++) {
            oa[no][0] *= c0f; oa[no][1] *= c0f;
            oa[no][2] *= c1f; oa[no][3] *= c1f;
        }

        uint32_t af[4][4];
        float sum0 = 0.f, sum1 = 0.f;
#pragma unroll
        for (int ni = 0; ni < 8; ni++) {
            half2 p0 = h2exp2(__floats2half2_rn((sf[ni][0] * SC - m0) * L2E,
                                                (sf[ni][1] * SC - m0) * L2E));
            half2 p1 = h2exp2(__floats2half2_rn((sf[ni][2] * SC - m1) * L2E,
                                                (sf[ni][3] * SC - m1) * L2E));
            float2 f0 = __half22float2(p0); sum0 += f0.x + f0.y;
            float2 f1 = __half22float2(p1); sum1 += f1.x + f1.y;
            const int ki = ni >> 1;
            if ((ni & 1) == 0) { af[ki][0] = h2_u32(p0); af[ki][1] = h2_u32(p1); }
            else               { af[ki][2] = h2_u32(p0); af[ki][3] = h2_u32(p1); }
        }
        l0 += sum0; l1 += sum1;

        // O += P V   (V^T in sv: B pairs contiguous along keys)
#pragma unroll
        for (int ki = 0; ki < 4; ki++) {
#pragma unroll
            for (int no = 0; no < 8; no++) {
                const half* vr = &sv[(no * 8 + g) * QPAD + ki * 16 + 2 * tig];
                uint32_t b0 = *(const uint32_t*)vr;
                uint32_t b1 = *(const uint32_t*)(vr + 8);
                mma16n8k16(oa[no], af[ki][0], af[ki][1], af[ki][2], af[ki][3], b0, b1);
            }
        }
    }

    // final normalize + write
    l0 += __shfl_xor_sync(~0u, l0, 1); l0 += __shfl_xor_sync(~0u, l0, 2);
    l1 += __shfl_xor_sync(~0u, l1, 1); l1 += __shfl_xor_sync(~0u, l1, 2);
    const float inv0 = 1.f / l0, inv1 = 1.f / l1;

    const int row0 = base_q + wq * 16 + g;
#pragma unroll
    for (int no = 0; no < 8; no++) {
        const int n = hoff + no * 8 + 2 * tig;
        *(float2*)&Op[(size_t)row0 * DMODEL + n] =
            make_float2(oa[no][0] * inv0, oa[no][1] * inv0);
        *(float2*)&Op[(size_t)(row0 + 8) * DMODEL + n] =
            make_float2(oa[no][2] * inv1, oa[no][3] * inv1);
    }
}

// ---------------- LayerNorm: one row per CTA, 256 threads -----------------------
__global__ void __launch_bounds__(256)
ln_kernel(const float* __restrict__ X, const float* __restrict__ gam,
          const float* __restrict__ bet, float* __restrict__ Y)
{
    const int row = blockIdx.x;
    const int t   = threadIdx.x;
    const int lane = t & 31, wid = t >> 5;
    const float* x = X + (size_t)row * DMODEL;

    float v0 = x[t], v1 = x[t + 256], v2 = x[t + 512];
    float s = v0 + v1 + v2;

    __shared__ float sbuf[8];
    __shared__ float s_mu, s_rstd;

#pragma unroll
    for (int o = 16; o > 0; o >>= 1) s += __shfl_xor_sync(~0u, s, o);
    if (lane == 0) sbuf[wid] = s;
    __syncthreads();
    if (t == 0) {
        float tot = 0.f;
        for (int i = 0; i < 8; i++) tot += sbuf[i];
        s_mu = tot * (1.0f / DMODEL);
    }
    __syncthreads();
    const float mu = s_mu;

    float d0 = v0 - mu, d1 = v1 - mu, d2 = v2 - mu;
    float qv = d0 * d0 + d1 * d1 + d2 * d2;
#pragma unroll
    for (int o = 16; o > 0; o >>= 1) qv += __shfl_xor_sync(~0u, qv, o);
    if (lane == 0) sbuf[wid] = qv;
    __syncthreads();
    if (t == 0) {
        float tot = 0.f;
        for (int i = 0; i < 8; i++) tot += sbuf[i];
        s_rstd = rsqrtf(tot * (1.0f / DMODEL) + LN_EPS);
    }
    __syncthreads();
    const float rstd = s_rstd;

    Y[(size_t)row * DMODEL + t      ] = d0 * rstd * gam[t      ] + bet[t      ];
    Y[(size_t)row * DMODEL + t + 256] = d1 * rstd * gam[t + 256] + bet[t + 256];
    Y[(size_t)row * DMODEL + t + 512] = d2 * rstd * gam[t + 512] + bet[t + 512];
}

// ---------------- launch --------------------------------------------------------
extern "C" void kernel_launch(void* const* d_in, const int* in_sizes, int n_in,
                              void* d_out, int out_size)
{
    const float* x    = (const float*)d_in[0];
    const float* x1   = (const float*)d_in[1];
    const float* Wq   = (const float*)d_in[2];
    const float* bq   = (const float*)d_in[3];
    const float* Wk   = (const float*)d_in[4];
    const float* bk   = (const float*)d_in[5];
    const float* Wv   = (const float*)d_in[6];
    const float* bv   = (const float*)d_in[7];
    const float* Wo   = (const float*)d_in[8];
    const float* bo   = (const float*)d_in[9];
    const float* W1   = (const float*)d_in[10];
    const float* b1   = (const float*)d_in[11];
    const float* W2   = (const float*)d_in[12];
    const float* b2   = (const float*)d_in[13];
    const float* ln1g = (const float*)d_in[14];
    const float* ln1b = (const float*)d_in[15];
    const float* ln2g = (const float*)d_in[16];
    const float* ln2b = (const float*)d_in[17];
    float* out = (float*)d_out;

    float *q, *k, *v, *o, *h, *h2, *f, *tbuf;
    cudaGetSymbolAddress((void**)&q,    g_q);
    cudaGetSymbolAddress((void**)&k,    g_k);
    cudaGetSymbolAddress((void**)&v,    g_v);
    cudaGetSymbolAddress((void**)&o,    g_o);
    cudaGetSymbolAddress((void**)&h,    g_h);
    cudaGetSymbolAddress((void**)&h2,   g_h2);
    cudaGetSymbolAddress((void**)&f,    g_f);
    cudaGetSymbolAddress((void**)&tbuf, g_t);

    const int SMB = 2 * BUF_H2 * 4;   // 40,960 bytes
    cudaFuncSetAttribute(gemm_mma, cudaFuncAttributeMaxDynamicSharedMemorySize, SMB);

    dim3 blk(256);
    dim3 g768(DMODEL / 128, NTOK / 128);   // (6, 64)
    dim3 gffn(DFFN / 128, NTOK / 128);     // (24, 64)

    gemm_mma<<<g768, blk, SMB>>>(x,  Wq, bq, nullptr, q, NTOK, DMODEL, DMODEL, 0);
    gemm_mma<<<g768, blk, SMB>>>(x1, Wk, bk, nullptr, k, NTOK, DMODEL, DMODEL, 0);
    gemm_mma<<<g768, blk, SMB>>>(x1, Wv, bv, nullptr, v, NTOK, DMODEL, DMODEL, 0);

    attn_mma<<<dim3(SEQ / 128, NH, NBATCH), 256>>>(q, k, v, o);

    gemm_mma<<<g768, blk, SMB>>>(o, Wo, bo, x, h, NTOK, DMODEL, DMODEL, 1);

    ln_kernel<<<NTOK, 256>>>(h, ln2g, ln2b, h2);

    gemm_mma<<<gffn, blk, SMB>>>(h2, W1, b1, nullptr, f, NTOK, DFFN, DMODEL, 2);
    gemm_mma<<<g768, blk, SMB>>>(f,  W2, b2, h, tbuf, NTOK, DMODEL, DFFN, 1);

    ln_kernel<<<NTOK, 256>>>(tbuf, ln1g, ln1b, out);
}